// round 8
// baseline (speedup 1.0000x reference)
#include <cuda_runtime.h>
#include <cuda_bf16.h>
#include <math.h>

#define NBR   4
#define Dd    256
#define SDIM  64
#define MEAS  320
#define MH    128
#define RH    64
#define UD    16
#define NOBS  25
#define BSZ   32768
#define HALL  512          // NBR*MH
#define K2    528          // HALL + UD
#define N2    288          // Dd + 32 (25 yt cols padded)
#define TM    64           // rows per CTA

// ---- device scratch (recomputed every launch; no allocs) ----
__device__ __nv_bfloat16 g_W1h[HALL * MEAS];
__device__ __nv_bfloat16 g_W1l[HALL * MEAS];
__device__ float g_M[NBR * Dd * RH];
__device__ float g_Mu[Dd * UD];
__device__ float g_Pf[Dd * HALL];
__device__ float g_zbias[Dd];
__device__ __nv_bfloat16 g_B2h[N2 * K2];
__device__ __nv_bfloat16 g_B2l[N2 * K2];
__device__ float g_bias2[N2];

// smem layout (bytes)
#define ROWB  2128                 // 532 floats per C1 row
#define OFF_C1 0
#define OFF_BH (TM * ROWB)         // 136192
#define OFF_BL (OFF_BH + N2 * 40)  // +11520
#define OFF_AH (OFF_BL + N2 * 40)
#define OFF_AL (OFF_AH + TM * 40)
#define OFF_U  (OFF_AL + TM * 40)
#define SMEM_TOTAL (OFF_U + TM * UD * 4)   // 168448

__device__ __forceinline__ void split_bf16(float v, __nv_bfloat16& hi, __nv_bfloat16& lo) {
    hi = __float2bfloat16(v);
    lo = __float2bfloat16(v - __bfloat162float(hi));
}

__device__ __forceinline__ void mma_bf16(float* d, const unsigned* a, const unsigned* b) {
    asm volatile(
        "mma.sync.aligned.m16n8k16.row.col.f32.bf16.bf16.f32 "
        "{%0,%1,%2,%3},{%4,%5,%6,%7},{%8,%9},{%0,%1,%2,%3};\n"
        : "+f"(d[0]), "+f"(d[1]), "+f"(d[2]), "+f"(d[3])
        : "r"(a[0]), "r"(a[1]), "r"(a[2]), "r"(a[3]), "r"(b[0]), "r"(b[1]));
}

// ======================= precompute kernels =======================
__global__ void pre_w1(const float* __restrict__ W1, const float* __restrict__ gates) {
    int e = blockIdx.x * 256 + threadIdx.x;
    if (e >= HALL * MEAS) return;
    int row = e / MEAS, k = e % MEAS;
    int n = row >> 7;
    float scale = 1.f;
    if (k < Dd) scale = 1.f / (1.f + expf(-gates[n * Dd + k]));
    split_bf16(W1[e] * scale, g_W1h[e], g_W1l[e]);
}

__global__ void pre_M_Mu(const float* __restrict__ Wout, const float* __restrict__ Bmat) {
    int e = blockIdx.x * 256 + threadIdx.x;
    if (e < NBR * Dd * RH) {
        int n = e / (Dd * RH);
        int rem = e % (Dd * RH);
        int d = rem / RH, j = rem % RH;
        const float* wr = Wout + (n * Dd + d) * RH;
        const float* br = Bmat + n * RH * (RH + UD) + j;
        float s = 0.f;
        #pragma unroll 8
        for (int r = 0; r < RH; r++) s += wr[r] * br[r * (RH + UD)];
        g_M[e] = s;
    } else {
        int e2 = e - NBR * Dd * RH;
        if (e2 < Dd * UD) {
            int d = e2 / UD, u = e2 % UD;
            float s = 0.f;
            for (int n = 0; n < NBR; n++) {
                const float* wr = Wout + (n * Dd + d) * RH;
                const float* br = Bmat + n * RH * (RH + UD) + RH + u;
                #pragma unroll 8
                for (int r = 0; r < RH; r++) s += wr[r] * br[r * (RH + UD)];
            }
            g_Mu[e2] = s;
        }
    }
}

__global__ void pre_P(const float* __restrict__ W2, const float* __restrict__ b2) {
    int e = blockIdx.x * 256 + threadIdx.x;
    if (e < NBR * Dd * MH) {
        int n = e / (Dd * MH);
        int rem = e % (Dd * MH);
        int d = rem / MH, h = rem % MH;
        const float* m = g_M + (n * Dd + d) * RH;
        const float* w = W2 + n * RH * MH + h;
        float s = 0.f;
        #pragma unroll 8
        for (int j = 0; j < RH; j++) s += m[j] * w[j * MH];
        g_Pf[d * HALL + n * MH + h] = s;
    } else if (e < NBR * Dd * MH + Dd) {
        int d = e - NBR * Dd * MH;
        float s = 0.f;
        for (int n = 0; n < NBR; n++) {
            const float* m = g_M + (n * Dd + d) * RH;
            const float* bb = b2 + n * RH;
            #pragma unroll 8
            for (int j = 0; j < RH; j++) s += m[j] * bb[j];
        }
        g_zbias[d] = s;
    }
}

__global__ void pre_B2(const float* __restrict__ C, const float* __restrict__ Dm) {
    int e = blockIdx.x * 256 + threadIdx.x;
    if (e >= N2 * K2) return;
    int n = e / K2, k = e % K2;
    float val = 0.f;
    if (n < Dd) {
        val = (k < HALL) ? g_Pf[n * HALL + k] : g_Mu[n * UD + (k - HALL)];
    } else if (n < Dd + NOBS) {
        int o = n - Dd;
        if (k < HALL) {
            float s = 0.f;
            #pragma unroll 8
            for (int d = 0; d < Dd; d++) s += C[o * Dd + d] * g_Pf[d * HALL + k];
            val = s;
        } else {
            int u = k - HALL;
            float s = Dm[o * UD + u];
            #pragma unroll 8
            for (int d = 0; d < Dd; d++) s += C[o * Dd + d] * g_Mu[d * UD + u];
            val = s;
        }
    }
    split_bf16(val, g_B2h[e], g_B2l[e]);
    if (k == 0) {
        float bv = 0.f;
        if (n < Dd) bv = g_zbias[n];
        else if (n < Dd + NOBS) {
            int o = n - Dd;
            float s = 0.f;
            #pragma unroll 8
            for (int d = 0; d < Dd; d++) s += C[o * Dd + d] * g_zbias[d];
            bv = s;
        }
        g_bias2[n] = bv;
    }
}

// ======================= main fused kernel =======================
__global__ __launch_bounds__(256, 1) void skolr_mma(
    const float* __restrict__ z_dyn, const float* __restrict__ z_static,
    const float* __restrict__ dtp,   const float* __restrict__ ut,
    const float* __restrict__ b1g,   const float* __restrict__ gammag,
    const float* __restrict__ betag, float* __restrict__ out)
{
    extern __shared__ char sm[];
    float* c1 = (float*)sm;                                  // [64][532] fp32, later hi/lo planes per row
    __nv_bfloat16* s_bh = (__nv_bfloat16*)(sm + OFF_BH);     // [288][20]
    __nv_bfloat16* s_bl = (__nv_bfloat16*)(sm + OFF_BL);
    __nv_bfloat16* s_ah = (__nv_bfloat16*)(sm + OFF_AH);     // [64][20]
    __nv_bfloat16* s_al = (__nv_bfloat16*)(sm + OFF_AL);
    float* s_u = (float*)(sm + OFF_U);                       // [64][16]

    const int tid = threadIdx.x;
    const int w = tid >> 5, lane = tid & 31;
    const int wm = w >> 1, wn = w & 1;
    const int g = lane >> 2, t4 = lane & 3;
    const int row0 = blockIdx.x * TM;
    const float dt = dtp[0];

    // stage u*dt
    for (int idx = tid; idx < TM * UD; idx += 256)
        s_u[idx] = ut[(size_t)(row0 + (idx >> 4)) * UD + (idx & 15)] * dt;

    // =============== GEMM1: C1[64][512] = X[64][320] * W1eff^T ===============
    for (int p = 0; p < 2; p++) {
        const int np0 = p * 256;
        float acc[16][4];
        #pragma unroll
        for (int i = 0; i < 16; i++)
            #pragma unroll
            for (int j = 0; j < 4; j++) acc[i][j] = 0.f;

        for (int kc = 0; kc < 20; kc++) {
            const int k0 = kc * 16;
            __syncthreads();
            // stage A chunk [64][16] split hi/lo
            #pragma unroll
            for (int idx = tid; idx < TM * 16; idx += 256) {
                int m = idx >> 4, k = idx & 15, gk = k0 + k;
                float v = (gk < Dd) ? z_dyn[(size_t)(row0 + m) * Dd + gk]
                                    : z_static[(size_t)(row0 + m) * SDIM + gk - Dd];
                __nv_bfloat16 hi, lo; split_bf16(v, hi, lo);
                s_ah[m * 20 + k] = hi; s_al[m * 20 + k] = lo;
            }
            // stage B chunk [256][16] from precomputed planes
            #pragma unroll
            for (int idx = tid; idx < 256 * 4; idx += 256) {
                int n = idx >> 2, j = idx & 3;
                *(uint2*)&s_bh[n * 20 + j * 4] = *(const uint2*)&g_W1h[(size_t)(np0 + n) * MEAS + k0 + j * 4];
                *(uint2*)&s_bl[n * 20 + j * 4] = *(const uint2*)&g_W1l[(size_t)(np0 + n) * MEAS + k0 + j * 4];
            }
            __syncthreads();

            const int ar = wm * 16 + g;
            unsigned ah[4], al[4];
            ah[0] = *(const unsigned*)(s_ah + ar * 20 + t4 * 2);
            ah[1] = *(const unsigned*)(s_ah + (ar + 8) * 20 + t4 * 2);
            ah[2] = *(const unsigned*)(s_ah + ar * 20 + t4 * 2 + 8);
            ah[3] = *(const unsigned*)(s_ah + (ar + 8) * 20 + t4 * 2 + 8);
            al[0] = *(const unsigned*)(s_al + ar * 20 + t4 * 2);
            al[1] = *(const unsigned*)(s_al + (ar + 8) * 20 + t4 * 2);
            al[2] = *(const unsigned*)(s_al + ar * 20 + t4 * 2 + 8);
            al[3] = *(const unsigned*)(s_al + (ar + 8) * 20 + t4 * 2 + 8);

            #pragma unroll
            for (int nt = 0; nt < 16; nt++) {
                const int br = wn * 128 + nt * 8 + g;
                unsigned bh[2], bl[2];
                bh[0] = *(const unsigned*)(s_bh + br * 20 + t4 * 2);
                bh[1] = *(const unsigned*)(s_bh + br * 20 + t4 * 2 + 8);
                bl[0] = *(const unsigned*)(s_bl + br * 20 + t4 * 2);
                bl[1] = *(const unsigned*)(s_bl + br * 20 + t4 * 2 + 8);
                mma_bf16(acc[nt], ah, bh);
                mma_bf16(acc[nt], ah, bl);
                mma_bf16(acc[nt], al, bh);
            }
        }
        // epilogue: +b1 -> fp32 C1
        #pragma unroll
        for (int nt = 0; nt < 16; nt++) {
            const int n0 = np0 + wn * 128 + nt * 8 + t4 * 2;
            const float b1a = __ldg(&b1g[n0]), b1b = __ldg(&b1g[n0 + 1]);
            float* c = c1 + (wm * 16 + g) * 532 + n0;
            c[0] = acc[nt][0] + b1a; c[1] = acc[nt][1] + b1b;
            c += 8 * 532;
            c[0] = acc[nt][2] + b1a; c[1] = acc[nt][3] + b1b;
        }
    }
    __syncthreads();

    // =============== per-branch LN(128) + exact GELU + repack hi/lo + append u ===============
    for (int rr = 0; rr < 8; rr++) {
        const int r = w * 8 + rr;
        const float* crow = c1 + r * 532;
        float v[16];
        #pragma unroll
        for (int j = 0; j < 16; j++) v[j] = crow[lane + 32 * j];
        float o[16];
        #pragma unroll
        for (int br = 0; br < 4; br++) {
            float s = 0.f, ss = 0.f;
            #pragma unroll
            for (int j = br * 4; j < br * 4 + 4; j++) { s += v[j]; ss = fmaf(v[j], v[j], ss); }
            #pragma unroll
            for (int off = 16; off > 0; off >>= 1) {
                s  += __shfl_xor_sync(0xffffffffu, s, off);
                ss += __shfl_xor_sync(0xffffffffu, ss, off);
            }
            const float mean = s * (1.f / 128.f);
            const float var  = ss * (1.f / 128.f) - mean * mean;
            const float inv  = rsqrtf(var + 1e-5f);
            #pragma unroll
            for (int j = br * 4; j < br * 4 + 4; j++) {
                const int col = lane + 32 * j;
                float t = (v[j] - mean) * inv * __ldg(&gammag[col]) + __ldg(&betag[col]);
                o[j] = 0.5f * t * (1.f + erff(t * 0.70710678118654752f));
            }
        }
        __syncwarp();
        char* rb = sm + r * ROWB;
        #pragma unroll
        for (int j = 0; j < 16; j++) {
            const int col = lane + 32 * j;
            __nv_bfloat16 hi, lo; split_bf16(o[j], hi, lo);
            *(__nv_bfloat16*)(rb + col * 2) = hi;
            *(__nv_bfloat16*)(rb + 1064 + col * 2) = lo;
        }
        if (lane < UD) {
            __nv_bfloat16 hi, lo; split_bf16(s_u[r * UD + lane], hi, lo);
            *(__nv_bfloat16*)(rb + (HALL + lane) * 2) = hi;
            *(__nv_bfloat16*)(rb + 1064 + (HALL + lane) * 2) = lo;
        }
    }
    __syncthreads();

    // =============== GEMM2: [64][288] = H'[64][528] * B2^T  (z_next + yt fused) ===============
    float acc2[18][4];
    #pragma unroll
    for (int i = 0; i < 18; i++)
        #pragma unroll
        for (int j = 0; j < 4; j++) acc2[i][j] = 0.f;

    for (int kc = 0; kc < 33; kc++) {
        const int k0 = kc * 16;
        __syncthreads();
        for (int idx = tid; idx < N2 * 4; idx += 256) {
            int n = idx >> 2, j = idx & 3;
            *(uint2*)&s_bh[n * 20 + j * 4] = *(const uint2*)&g_B2h[(size_t)n * K2 + k0 + j * 4];
            *(uint2*)&s_bl[n * 20 + j * 4] = *(const uint2*)&g_B2l[(size_t)n * K2 + k0 + j * 4];
        }
        __syncthreads();

        const int ar = wm * 16 + g;
        const char* ra = sm + ar * ROWB;
        const char* rb2 = sm + (ar + 8) * ROWB;
        const int kb = (k0 + t4 * 2) * 2;
        unsigned ah[4], al[4];
        ah[0] = *(const unsigned*)(ra + kb);
        ah[1] = *(const unsigned*)(rb2 + kb);
        ah[2] = *(const unsigned*)(ra + kb + 16);
        ah[3] = *(const unsigned*)(rb2 + kb + 16);
        al[0] = *(const unsigned*)(ra + 1064 + kb);
        al[1] = *(const unsigned*)(rb2 + 1064 + kb);
        al[2] = *(const unsigned*)(ra + 1064 + kb + 16);
        al[3] = *(const unsigned*)(rb2 + 1064 + kb + 16);

        #pragma unroll
        for (int nt = 0; nt < 18; nt++) {
            const int br = wn * 144 + nt * 8 + g;
            unsigned bh[2], bl[2];
            bh[0] = *(const unsigned*)(s_bh + br * 20 + t4 * 2);
            bh[1] = *(const unsigned*)(s_bh + br * 20 + t4 * 2 + 8);
            bl[0] = *(const unsigned*)(s_bl + br * 20 + t4 * 2);
            bl[1] = *(const unsigned*)(s_bl + br * 20 + t4 * 2 + 8);
            mma_bf16(acc2[nt], ah, bh);
            mma_bf16(acc2[nt], ah, bl);
            mma_bf16(acc2[nt], al, bh);
        }
    }

    // epilogue: + bias2, write z_next and yt
    float* out_yt = out + (size_t)BSZ * Dd;
    #pragma unroll
    for (int nt = 0; nt < 18; nt++) {
        const int n0 = wn * 144 + nt * 8 + t4 * 2;
        const float ba = __ldg(&g_bias2[n0]), bb = __ldg(&g_bias2[n0 + 1]);
        const int r = wm * 16 + g;
        float v0 = acc2[nt][0] + ba, v1 = acc2[nt][1] + bb;
        float v2 = acc2[nt][2] + ba, v3 = acc2[nt][3] + bb;
        if (n0 < Dd) {
            *(float2*)&out[(size_t)(row0 + r) * Dd + n0]     = make_float2(v0, v1);
            *(float2*)&out[(size_t)(row0 + r + 8) * Dd + n0] = make_float2(v2, v3);
        } else {
            const int o = n0 - Dd;
            if (o < NOBS)     { out_yt[(size_t)(row0 + r) * NOBS + o]     = v0;
                                out_yt[(size_t)(row0 + r + 8) * NOBS + o] = v2; }
            if (o + 1 < NOBS) { out_yt[(size_t)(row0 + r) * NOBS + o + 1]     = v1;
                                out_yt[(size_t)(row0 + r + 8) * NOBS + o + 1] = v3; }
        }
    }
}

extern "C" void kernel_launch(void* const* d_in, const int* in_sizes, int n_in,
                              void* d_out, int out_size) {
    const float* z_dyn    = (const float*)d_in[0];
    const float* z_static = (const float*)d_in[1];
    const float* dt       = (const float*)d_in[2];
    const float* ut       = (const float*)d_in[3];
    const float* gates    = (const float*)d_in[4];
    const float* W1       = (const float*)d_in[5];
    const float* b1       = (const float*)d_in[6];
    const float* gamma    = (const float*)d_in[7];
    const float* beta     = (const float*)d_in[8];
    const float* W2       = (const float*)d_in[9];
    const float* b2       = (const float*)d_in[10];
    const float* Bmat     = (const float*)d_in[13];
    const float* Wout     = (const float*)d_in[14];
    const float* Cmat     = (const float*)d_in[15];
    const float* Dm       = (const float*)d_in[16];
    float* out = (float*)d_out;

    pre_w1<<<(HALL * MEAS + 255) / 256, 256>>>(W1, gates);
    pre_M_Mu<<<(NBR * Dd * RH + Dd * UD + 255) / 256, 256>>>(Wout, Bmat);
    pre_P<<<(NBR * Dd * MH + Dd + 255) / 256, 256>>>(W2, b2);
    pre_B2<<<(N2 * K2 + 255) / 256, 256>>>(Cmat, Dm);

    cudaFuncSetAttribute(skolr_mma, cudaFuncAttributeMaxDynamicSharedMemorySize, SMEM_TOTAL);
    skolr_mma<<<BSZ / TM, 256, SMEM_TOTAL>>>(z_dyn, z_static, dt, ut, b1, gamma, beta, out);
}

// round 10
// speedup vs baseline: 1.3555x; 1.3555x over previous
#include <cuda_runtime.h>
#include <cuda_bf16.h>
#include <math.h>
#include <stdint.h>

#define NBR 4
#define Dd 256
#define SDIM 64
#define MEAS 320
#define MH 128
#define RH 64
#define UD 16
#define NOBS 25
#define BSZ 32768
#define HALL 512
#define K2 528
#define N2 288
#define TM 64

__device__ __nv_bfloat16 g_W1h[HALL * MEAS];
__device__ __nv_bfloat16 g_W1l[HALL * MEAS];
__device__ float g_M[NBR * Dd * RH];
__device__ float g_Mu[Dd * UD];
__device__ float g_Pf[Dd * HALL];
__device__ float g_zbias[Dd];
__device__ __nv_bfloat16 g_B2h[N2 * K2];
__device__ __nv_bfloat16 g_B2l[N2 * K2];
__device__ float g_bias2[N2];

// ---- smem layout (bytes) ----
// H: [64 rows][536 bf16] x 2 planes (hi, lo). Row stride 1072B -> conflict-free ldmatrix.
#define HSTR 1072
#define HP   68608                 // 64*1072
#define OFF_BB 137216              // B tiles: 2 bufs x 2 planes x 288*48
#define BBUF 27648
#define BPL  13824
#define OFF_AB 192512              // A tiles (GEMM1): 2 bufs x 2 planes x 64*48
#define ABUF 6144
#define APL  3072
#define SMEM_TOTAL 204800

#define CPA(dst, src) asm volatile("cp.async.cg.shared.global [%0], [%1], 16;" :: "r"(dst), "l"(src))
#define CPC()  asm volatile("cp.async.commit_group;")
#define CPW1() asm volatile("cp.async.wait_group 1;")
#define CPW0() asm volatile("cp.async.wait_group 0;")

#define LDSM4(r, a) \
    asm volatile("ldmatrix.sync.aligned.m8n8.x4.shared.b16 {%0,%1,%2,%3}, [%4];" \
        : "=r"((r)[0]), "=r"((r)[1]), "=r"((r)[2]), "=r"((r)[3]) : "r"(a))

__device__ __forceinline__ void mma_bf16(float* d, const uint32_t* a, const uint32_t* b) {
    asm volatile(
        "mma.sync.aligned.m16n8k16.row.col.f32.bf16.bf16.f32 "
        "{%0,%1,%2,%3},{%4,%5,%6,%7},{%8,%9},{%0,%1,%2,%3};\n"
        : "+f"(d[0]), "+f"(d[1]), "+f"(d[2]), "+f"(d[3])
        : "r"(a[0]), "r"(a[1]), "r"(a[2]), "r"(a[3]), "r"(b[0]), "r"(b[1]));
}
__device__ __forceinline__ void split2(float v, __nv_bfloat16& hi, __nv_bfloat16& lo) {
    hi = __float2bfloat16(v);
    lo = __float2bfloat16(v - __bfloat162float(hi));
}
__device__ __forceinline__ uint32_t smem_u32(const void* p) {
    uint32_t a;
    asm("{ .reg .u64 t; cvta.to.shared.u64 t, %1; cvt.u32.u64 %0, t; }" : "=r"(a) : "l"(p));
    return a;
}

// ======================= precompute =======================
__global__ void pre_w1(const float* __restrict__ W1, const float* __restrict__ gates) {
    int e = blockIdx.x * 256 + threadIdx.x;
    if (e >= HALL * MEAS) return;
    int row = e / MEAS, k = e % MEAS, n = row >> 7;
    float sc = 1.f;
    if (k < Dd) sc = 1.f / (1.f + expf(-gates[n * Dd + k]));
    split2(W1[e] * sc, g_W1h[e], g_W1l[e]);
}
__global__ void pre_M_Mu(const float* __restrict__ Wout, const float* __restrict__ Bmat) {
    int e = blockIdx.x * 256 + threadIdx.x;
    if (e < NBR * Dd * RH) {
        int n = e / (Dd * RH), rem = e % (Dd * RH), d = rem / RH, j = rem % RH;
        const float* wr = Wout + (n * Dd + d) * RH;
        const float* br = Bmat + n * RH * (RH + UD) + j;
        float s = 0.f;
        #pragma unroll 8
        for (int r = 0; r < RH; r++) s += wr[r] * br[r * (RH + UD)];
        g_M[e] = s;
    } else {
        int e2 = e - NBR * Dd * RH;
        if (e2 < Dd * UD) {
            int d = e2 / UD, u = e2 % UD;
            float s = 0.f;
            for (int n = 0; n < NBR; n++) {
                const float* wr = Wout + (n * Dd + d) * RH;
                const float* br = Bmat + n * RH * (RH + UD) + RH + u;
                #pragma unroll 8
                for (int r = 0; r < RH; r++) s += wr[r] * br[r * (RH + UD)];
            }
            g_Mu[e2] = s;
        }
    }
}
__global__ void pre_P(const float* __restrict__ W2, const float* __restrict__ b2) {
    int e = blockIdx.x * 256 + threadIdx.x;
    if (e < NBR * Dd * MH) {
        int n = e / (Dd * MH), rem = e % (Dd * MH), d = rem / MH, h = rem % MH;
        const float* m = g_M + (n * Dd + d) * RH;
        const float* w = W2 + n * RH * MH + h;
        float s = 0.f;
        #pragma unroll 8
        for (int j = 0; j < RH; j++) s += m[j] * w[j * MH];
        g_Pf[d * HALL + n * MH + h] = s;
    } else if (e < NBR * Dd * MH + Dd) {
        int d = e - NBR * Dd * MH;
        float s = 0.f;
        for (int n = 0; n < NBR; n++) {
            const float* m = g_M + (n * Dd + d) * RH;
            const float* bb = b2 + n * RH;
            #pragma unroll 8
            for (int j = 0; j < RH; j++) s += m[j] * bb[j];
        }
        g_zbias[d] = s;
    }
}
__global__ void pre_B2a() {   // z rows: identity fold
    int e = blockIdx.x * 256 + threadIdx.x;
    if (e >= Dd * K2) return;
    int n = e / K2, k = e % K2;
    float v = (k < HALL) ? g_Pf[n * HALL + k] : g_Mu[n * UD + (k - HALL)];
    split2(v, g_B2h[e], g_B2l[e]);
    if (k == 0) g_bias2[n] = g_zbias[n];
}
__global__ void pre_B2b(const float* __restrict__ C, const float* __restrict__ Dm) {
    __shared__ float sC[Dd];
    int o = blockIdx.x, tid = threadIdx.x, n = Dd + o;
    if (o >= NOBS) {
        for (int k = tid; k < K2; k += 256) {
            g_B2h[n * K2 + k] = __float2bfloat16(0.f);
            g_B2l[n * K2 + k] = __float2bfloat16(0.f);
        }
        if (tid == 0) g_bias2[n] = 0.f;
        return;
    }
    sC[tid] = C[o * Dd + tid];
    __syncthreads();
    for (int k = tid; k < K2; k += 256) {
        float s;
        if (k < HALL) {
            s = 0.f;
            #pragma unroll 8
            for (int d = 0; d < Dd; d++) s += sC[d] * g_Pf[d * HALL + k];
        } else {
            int u = k - HALL;
            s = Dm[o * UD + u];
            #pragma unroll 8
            for (int d = 0; d < Dd; d++) s += sC[d] * g_Mu[d * UD + u];
        }
        split2(s, g_B2h[n * K2 + k], g_B2l[n * K2 + k]);
    }
    if (tid == 0) {
        float s = 0.f;
        #pragma unroll 8
        for (int d = 0; d < Dd; d++) s += sC[d] * g_zbias[d];
        g_bias2[n] = s;
    }
}

// ======================= main kernel =======================
__global__ __launch_bounds__(256, 1) void skolr2(
    const float* __restrict__ z_dyn, const float* __restrict__ z_static,
    const float* __restrict__ dtp,   const float* __restrict__ ut,
    const float* __restrict__ b1g,   const float* __restrict__ gammag,
    const float* __restrict__ betag, float* __restrict__ out)
{
    extern __shared__ char sm[];
    const uint32_t smb = smem_u32(sm);
    const int tid = threadIdx.x, w = tid >> 5, lane = tid & 31;
    const int wm = w >> 1, wn = w & 1;
    const int g = lane >> 2, t4 = lane & 3;
    const int row0 = blockIdx.x * TM;
    const float dt = dtp[0];

    // ldmatrix per-lane offsets
    const int sub = lane >> 3;
    const uint32_t aRow = ((uint32_t)(sub & 1)) * 8 + (lane & 7);  // A: m0 r0-7,k0-7 | m1 r8-15,k0-7 | m2 r0-7,k8-15 | m3 r8-15,k8-15
    const uint32_t aCh  = ((uint32_t)(sub >> 1)) * 16;
    const uint32_t bRow = ((uint32_t)(sub >> 1)) * 8 + (lane & 7); // B: m0 n0-7,k0-7 | m1 n0-7,k8-15 | m2 n8-15,k0-7 | m3 n8-15,k8-15
    const uint32_t bCh  = ((uint32_t)(sub & 1)) * 16;

    // ---- u*dt into H columns 512..527 (hi/lo planes) ----
    {
        int m = tid >> 2, q = tid & 3;
        float4 f = *(const float4*)&ut[(size_t)(row0 + m) * UD + q * 4];
        f.x *= dt; f.y *= dt; f.z *= dt; f.w *= dt;
        __nv_bfloat16 h0, l0, h1, l1, h2, l2, h3, l3;
        split2(f.x, h0, l0); split2(f.y, h1, l1); split2(f.z, h2, l2); split2(f.w, h3, l3);
        uint2 hp, lp;
        hp.x = (uint32_t)__bfloat16_as_ushort(h0) | ((uint32_t)__bfloat16_as_ushort(h1) << 16);
        hp.y = (uint32_t)__bfloat16_as_ushort(h2) | ((uint32_t)__bfloat16_as_ushort(h3) << 16);
        lp.x = (uint32_t)__bfloat16_as_ushort(l0) | ((uint32_t)__bfloat16_as_ushort(l1) << 16);
        lp.y = (uint32_t)__bfloat16_as_ushort(l2) | ((uint32_t)__bfloat16_as_ushort(l3) << 16);
        *(uint2*)(sm + m * HSTR + 1024 + q * 8)      = hp;
        *(uint2*)(sm + HP + m * HSTR + 1024 + q * 8) = lp;
    }

    // ================= GEMM1 (2 halves of 256 output cols) + fused LN/GELU =================
    for (int p = 0; p < 2; p++) {
        float acc[16][4];
        #pragma unroll
        for (int i = 0; i < 16; i++) { acc[i][0] = acc[i][1] = acc[i][2] = acc[i][3] = 0.f; }

        // stage chunk kc into buffer buf: A (convert+split) and B (cp.async)
        #define STAGE1(kc_, buf_) do { \
            int _kc = (kc_), _bf = (buf_); \
            { int m = tid >> 2, q = tid & 3; \
              float4 f = (_kc < 16) \
                ? *(const float4*)&z_dyn[(size_t)(row0 + m) * Dd + _kc * 16 + q * 4] \
                : *(const float4*)&z_static[(size_t)(row0 + m) * SDIM + (_kc - 16) * 16 + q * 4]; \
              __nv_bfloat16 h0, l0, h1, l1, h2, l2, h3, l3; \
              split2(f.x, h0, l0); split2(f.y, h1, l1); split2(f.z, h2, l2); split2(f.w, h3, l3); \
              uint2 hp, lp; \
              hp.x = (uint32_t)__bfloat16_as_ushort(h0) | ((uint32_t)__bfloat16_as_ushort(h1) << 16); \
              hp.y = (uint32_t)__bfloat16_as_ushort(h2) | ((uint32_t)__bfloat16_as_ushort(h3) << 16); \
              lp.x = (uint32_t)__bfloat16_as_ushort(l0) | ((uint32_t)__bfloat16_as_ushort(l1) << 16); \
              lp.y = (uint32_t)__bfloat16_as_ushort(l2) | ((uint32_t)__bfloat16_as_ushort(l3) << 16); \
              char* ab = sm + OFF_AB + _bf * ABUF + m * 48 + q * 8; \
              *(uint2*)ab = hp; *(uint2*)(ab + APL) = lp; } \
            _Pragma("unroll") \
            for (int t = 0; t < 4; t++) { \
                int comp = tid + t * 256; \
                int n = comp & 255, h16 = (comp >> 8) & 1, pl = comp >> 9; \
                const __nv_bfloat16* src = (pl ? g_W1l : g_W1h) + (size_t)(p * 256 + n) * MEAS + _kc * 16 + h16 * 8; \
                uint32_t dst = smb + OFF_BB + _bf * BBUF + pl * BPL + n * 48 + h16 * 16; \
                CPA(dst, src); \
            } \
        } while (0)

        STAGE1(0, 0); CPC();
        for (int kc = 0; kc < 20; kc++) {
            if (kc < 19) { STAGE1(kc + 1, (kc + 1) & 1); CPC(); CPW1(); } else { CPW0(); }
            __syncthreads();
            const int buf = kc & 1;
            uint32_t ah[4], al[4];
            uint32_t aaddr = smb + OFF_AB + buf * ABUF + (wm * 16 + aRow) * 48 + aCh;
            LDSM4(ah, aaddr); LDSM4(al, aaddr + APL);
            uint32_t bh[32], bl[32];
            uint32_t bbase = smb + OFF_BB + buf * BBUF + (wn * 128 + bRow) * 48 + bCh;
            #pragma unroll
            for (int q = 0; q < 8; q++) {
                uint32_t ba = bbase + q * (16 * 48);
                LDSM4(&bh[q * 4], ba); LDSM4(&bl[q * 4], ba + BPL);
            }
            #pragma unroll
            for (int nt = 0; nt < 16; nt++) {
                const uint32_t* bhp = &bh[(nt >> 1) * 4 + (nt & 1) * 2];
                const uint32_t* blp = &bl[(nt >> 1) * 4 + (nt & 1) * 2];
                mma_bf16(acc[nt], ah, bhp);
                mma_bf16(acc[nt], ah, blp);
                mma_bf16(acc[nt], al, bhp);
            }
            __syncthreads();
        }
        #undef STAGE1

        // ---- epilogue: +b1, LN(128) via t4 shuffles, GELU, split -> H ----
        float s0 = 0.f, q0 = 0.f, s1 = 0.f, q1 = 0.f;
        #pragma unroll
        for (int nt = 0; nt < 16; nt++) {
            int c = p * 256 + wn * 128 + nt * 8 + t4 * 2;
            float ba = __ldg(&b1g[c]), bb = __ldg(&b1g[c + 1]);
            acc[nt][0] += ba; acc[nt][1] += bb; acc[nt][2] += ba; acc[nt][3] += bb;
            s0 += acc[nt][0] + acc[nt][1];
            q0 = fmaf(acc[nt][0], acc[nt][0], fmaf(acc[nt][1], acc[nt][1], q0));
            s1 += acc[nt][2] + acc[nt][3];
            q1 = fmaf(acc[nt][2], acc[nt][2], fmaf(acc[nt][3], acc[nt][3], q1));
        }
        #pragma unroll
        for (int o = 1; o <= 2; o <<= 1) {
            s0 += __shfl_xor_sync(0xffffffffu, s0, o);
            q0 += __shfl_xor_sync(0xffffffffu, q0, o);
            s1 += __shfl_xor_sync(0xffffffffu, s1, o);
            q1 += __shfl_xor_sync(0xffffffffu, q1, o);
        }
        const float mean0 = s0 * (1.f / 128.f);
        const float inv0  = rsqrtf(q0 * (1.f / 128.f) - mean0 * mean0 + 1e-5f);
        const float mean1 = s1 * (1.f / 128.f);
        const float inv1  = rsqrtf(q1 * (1.f / 128.f) - mean1 * mean1 + 1e-5f);
        const int rA = wm * 16 + g, rB = rA + 8;
        #pragma unroll
        for (int nt = 0; nt < 16; nt++) {
            int c = p * 256 + wn * 128 + nt * 8 + t4 * 2;
            float ga = __ldg(&gammag[c]), gb = __ldg(&gammag[c + 1]);
            float ea = __ldg(&betag[c]),  eb = __ldg(&betag[c + 1]);
            float t0 = (acc[nt][0] - mean0) * inv0 * ga + ea;
            float t1 = (acc[nt][1] - mean0) * inv0 * gb + eb;
            float t2 = (acc[nt][2] - mean1) * inv1 * ga + ea;
            float t3 = (acc[nt][3] - mean1) * inv1 * gb + eb;
            t0 = 0.5f * t0 * (1.f + erff(t0 * 0.70710678118654752f));
            t1 = 0.5f * t1 * (1.f + erff(t1 * 0.70710678118654752f));
            t2 = 0.5f * t2 * (1.f + erff(t2 * 0.70710678118654752f));
            t3 = 0.5f * t3 * (1.f + erff(t3 * 0.70710678118654752f));
            __nv_bfloat16 x0, y0, x1, y1, x2, y2, x3, y3;
            split2(t0, x0, y0); split2(t1, x1, y1); split2(t2, x2, y2); split2(t3, x3, y3);
            uint32_t hA = (uint32_t)__bfloat16_as_ushort(x0) | ((uint32_t)__bfloat16_as_ushort(x1) << 16);
            uint32_t lA = (uint32_t)__bfloat16_as_ushort(y0) | ((uint32_t)__bfloat16_as_ushort(y1) << 16);
            uint32_t hB = (uint32_t)__bfloat16_as_ushort(x2) | ((uint32_t)__bfloat16_as_ushort(x3) << 16);
            uint32_t lB = (uint32_t)__bfloat16_as_ushort(y2) | ((uint32_t)__bfloat16_as_ushort(y3) << 16);
            *(uint32_t*)(sm + rA * HSTR + c * 2)      = hA;
            *(uint32_t*)(sm + HP + rA * HSTR + c * 2) = lA;
            *(uint32_t*)(sm + rB * HSTR + c * 2)      = hB;
            *(uint32_t*)(sm + HP + rB * HSTR + c * 2) = lB;
        }
    }

    // ================= GEMM2: [64][288] = H[64][528] x B2^T =================
    float acc2[18][4];
    #pragma unroll
    for (int i = 0; i < 18; i++) { acc2[i][0] = acc2[i][1] = acc2[i][2] = acc2[i][3] = 0.f; }

    #define STAGE2(kc_, buf_) do { \
        int _kc = (kc_), _bf = (buf_); \
        for (int idx = tid; idx < 1152; idx += 256) { \
            int pl = idx / 576, rem = idx % 576, n = rem >> 1, h16 = rem & 1; \
            const __nv_bfloat16* src = (pl ? g_B2l : g_B2h) + (size_t)n * K2 + _kc * 16 + h16 * 8; \
            uint32_t dst = smb + OFF_BB + _bf * BBUF + pl * BPL + n * 48 + h16 * 16; \
            CPA(dst, src); \
        } \
    } while (0)

    STAGE2(0, 0); CPC();
    for (int kc = 0; kc < 33; kc++) {
        if (kc < 32) { STAGE2(kc + 1, (kc + 1) & 1); CPC(); CPW1(); } else { CPW0(); }
        __syncthreads();
        const int buf = kc & 1;
        uint32_t ah[4], al[4];
        uint32_t aaddr = smb + (wm * 16 + aRow) * HSTR + kc * 32 + aCh;
        LDSM4(ah, aaddr); LDSM4(al, aaddr + HP);
        uint32_t bh[36], bl[36];
        uint32_t bbase = smb + OFF_BB + buf * BBUF + (wn * 144 + bRow) * 48 + bCh;
        #pragma unroll
        for (int q = 0; q < 9; q++) {
            uint32_t ba = bbase + q * (16 * 48);
            LDSM4(&bh[q * 4], ba); LDSM4(&bl[q * 4], ba + BPL);
        }
        #pragma unroll
        for (int nt = 0; nt < 18; nt++) {
            const uint32_t* bhp = &bh[(nt >> 1) * 4 + (nt & 1) * 2];
            const uint32_t* blp = &bl[(nt >> 1) * 4 + (nt & 1) * 2];
            mma_bf16(acc2[nt], ah, bhp);
            mma_bf16(acc2[nt], ah, blp);
            mma_bf16(acc2[nt], al, bhp);
        }
        __syncthreads();
    }
    #undef STAGE2

    // ---- epilogue: +bias2; write z_next and yt ----
    float* out_yt = out + (size_t)BSZ * Dd;
    #pragma unroll
    for (int nt = 0; nt < 18; nt++) {
        const int n0 = wn * 144 + nt * 8 + t4 * 2;
        const float ba = __ldg(&g_bias2[n0]), bb = __ldg(&g_bias2[n0 + 1]);
        const int r = wm * 16 + g;
        float v0 = acc2[nt][0] + ba, v1 = acc2[nt][1] + bb;
        float v2 = acc2[nt][2] + ba, v3 = acc2[nt][3] + bb;
        if (n0 < Dd) {
            *(float2*)&out[(size_t)(row0 + r) * Dd + n0]     = make_float2(v0, v1);
            *(float2*)&out[(size_t)(row0 + r + 8) * Dd + n0] = make_float2(v2, v3);
        } else {
            const int o = n0 - Dd;
            if (o < NOBS)     { out_yt[(size_t)(row0 + r) * NOBS + o]     = v0;
                                out_yt[(size_t)(row0 + r + 8) * NOBS + o] = v2; }
            if (o + 1 < NOBS) { out_yt[(size_t)(row0 + r) * NOBS + o + 1]     = v1;
                                out_yt[(size_t)(row0 + r + 8) * NOBS + o + 1] = v3; }
        }
    }
}

extern "C" void kernel_launch(void* const* d_in, const int* in_sizes, int n_in,
                              void* d_out, int out_size) {
    const float* z_dyn    = (const float*)d_in[0];
    const float* z_static = (const float*)d_in[1];
    const float* dt       = (const float*)d_in[2];
    const float* ut       = (const float*)d_in[3];
    const float* gates    = (const float*)d_in[4];
    const float* W1       = (const float*)d_in[5];
    const float* b1       = (const float*)d_in[6];
    const float* gamma    = (const float*)d_in[7];
    const float* beta     = (const float*)d_in[8];
    const float* W2       = (const float*)d_in[9];
    const float* b2       = (const float*)d_in[10];
    const float* Bmat     = (const float*)d_in[13];
    const float* Wout     = (const float*)d_in[14];
    const float* Cmat     = (const float*)d_in[15];
    const float* Dm       = (const float*)d_in[16];
    float* out = (float*)d_out;

    pre_w1<<<(HALL * MEAS + 255) / 256, 256>>>(W1, gates);
    pre_M_Mu<<<(NBR * Dd * RH + Dd * UD + 255) / 256, 256>>>(Wout, Bmat);
    pre_P<<<(NBR * Dd * MH + Dd + 255) / 256, 256>>>(W2, b2);
    pre_B2a<<<(Dd * K2 + 255) / 256, 256>>>();
    pre_B2b<<<N2 - Dd, 256>>>(Cmat, Dm);

    cudaFuncSetAttribute(skolr2, cudaFuncAttributeMaxDynamicSharedMemorySize, SMEM_TOTAL);
    skolr2<<<BSZ / TM, 256, SMEM_TOTAL>>>(z_dyn, z_static, dt, ut, b1, gamma, beta, out);
}

// round 11
// speedup vs baseline: 1.3584x; 1.0021x over previous
#include <cuda_runtime.h>
#include <cuda_bf16.h>
#include <math.h>
#include <stdint.h>

#define NBR 4
#define Dd 256
#define SDIM 64
#define MEAS 320
#define MH 128
#define RH 64
#define UD 16
#define NOBS 25
#define BSZ 32768
#define HALL 512
#define K2 528
#define N2 288
#define TM 64

__device__ __nv_bfloat16 g_W1h[HALL * MEAS];
__device__ __nv_bfloat16 g_W1l[HALL * MEAS];
__device__ float g_M[NBR * Dd * RH];
__device__ float g_Mu[Dd * UD];
__device__ float g_Pf[Dd * HALL];
__device__ float g_zbias[Dd];
__device__ __nv_bfloat16 g_B2h[N2 * K2];
__device__ __nv_bfloat16 g_B2l[N2 * K2];
__device__ float g_bias2[N2];

// ---- smem layout (bytes) ----
#define HSTR 1072
#define HP   68608
#define OFF_BB 137216
#define BBUF 27648
#define BPL  13824
#define OFF_AB 192512
#define ABUF 6144
#define APL  3072
#define SMEM_TOTAL 204800

#define CPA(dst, src) asm volatile("cp.async.cg.shared.global [%0], [%1], 16;" :: "r"(dst), "l"(src))
#define CPC()  asm volatile("cp.async.commit_group;")
#define CPW1() asm volatile("cp.async.wait_group 1;")
#define CPW0() asm volatile("cp.async.wait_group 0;")

#define LDSM4(r, a) \
    asm volatile("ldmatrix.sync.aligned.m8n8.x4.shared.b16 {%0,%1,%2,%3}, [%4];" \
        : "=r"((r)[0]), "=r"((r)[1]), "=r"((r)[2]), "=r"((r)[3]) : "r"(a))

__device__ __forceinline__ void mma_bf16(float* d, const uint32_t* a, const uint32_t* b) {
    asm volatile(
        "mma.sync.aligned.m16n8k16.row.col.f32.bf16.bf16.f32 "
        "{%0,%1,%2,%3},{%4,%5,%6,%7},{%8,%9},{%0,%1,%2,%3};\n"
        : "+f"(d[0]), "+f"(d[1]), "+f"(d[2]), "+f"(d[3])
        : "r"(a[0]), "r"(a[1]), "r"(a[2]), "r"(a[3]), "r"(b[0]), "r"(b[1]));
}
__device__ __forceinline__ void split2(float v, __nv_bfloat16& hi, __nv_bfloat16& lo) {
    hi = __float2bfloat16(v);
    lo = __float2bfloat16(v - __bfloat162float(hi));
}
__device__ __forceinline__ uint32_t smem_u32(const void* p) {
    uint32_t a;
    asm("{ .reg .u64 t; cvta.to.shared.u64 t, %1; cvt.u32.u64 %0, t; }" : "=r"(a) : "l"(p));
    return a;
}

// ======================= precompute =======================
__global__ void pre_w1(const float* __restrict__ W1, const float* __restrict__ gates) {
    int e = blockIdx.x * 256 + threadIdx.x;
    if (e >= HALL * MEAS) return;
    int row = e / MEAS, k = e % MEAS, n = row >> 7;
    float sc = 1.f;
    if (k < Dd) sc = 1.f / (1.f + expf(-gates[n * Dd + k]));
    split2(W1[e] * sc, g_W1h[e], g_W1l[e]);
}
__global__ void pre_M_Mu(const float* __restrict__ Wout, const float* __restrict__ Bmat) {
    int e = blockIdx.x * 256 + threadIdx.x;
    if (e < NBR * Dd * RH) {
        int n = e / (Dd * RH), rem = e % (Dd * RH), d = rem / RH, j = rem % RH;
        const float* wr = Wout + (n * Dd + d) * RH;
        const float* br = Bmat + n * RH * (RH + UD) + j;
        float s = 0.f;
        #pragma unroll 8
        for (int r = 0; r < RH; r++) s += wr[r] * br[r * (RH + UD)];
        g_M[e] = s;
    } else {
        int e2 = e - NBR * Dd * RH;
        if (e2 < Dd * UD) {
            int d = e2 / UD, u = e2 % UD;
            float s = 0.f;
            for (int n = 0; n < NBR; n++) {
                const float* wr = Wout + (n * Dd + d) * RH;
                const float* br = Bmat + n * RH * (RH + UD) + RH + u;
                #pragma unroll 8
                for (int r = 0; r < RH; r++) s += wr[r] * br[r * (RH + UD)];
            }
            g_Mu[e2] = s;
        }
    }
}
__global__ void pre_P(const float* __restrict__ W2, const float* __restrict__ b2) {
    int e = blockIdx.x * 256 + threadIdx.x;
    if (e < NBR * Dd * MH) {
        int n = e / (Dd * MH), rem = e % (Dd * MH), d = rem / MH, h = rem % MH;
        const float* m = g_M + (n * Dd + d) * RH;
        const float* w = W2 + n * RH * MH + h;
        float s = 0.f;
        #pragma unroll 8
        for (int j = 0; j < RH; j++) s += m[j] * w[j * MH];
        g_Pf[d * HALL + n * MH + h] = s;
    } else if (e < NBR * Dd * MH + Dd) {
        int d = e - NBR * Dd * MH;
        float s = 0.f;
        for (int n = 0; n < NBR; n++) {
            const float* m = g_M + (n * Dd + d) * RH;
            const float* bb = b2 + n * RH;
            #pragma unroll 8
            for (int j = 0; j < RH; j++) s += m[j] * bb[j];
        }
        g_zbias[d] = s;
    }
}
__global__ void pre_B2a() {
    int e = blockIdx.x * 256 + threadIdx.x;
    if (e >= Dd * K2) return;
    int n = e / K2, k = e % K2;
    float v = (k < HALL) ? g_Pf[n * HALL + k] : g_Mu[n * UD + (k - HALL)];
    split2(v, g_B2h[e], g_B2l[e]);
    if (k == 0) g_bias2[n] = g_zbias[n];
}
__global__ void pre_B2b(const float* __restrict__ C, const float* __restrict__ Dm) {
    __shared__ float sC[Dd];
    int o = blockIdx.x, tid = threadIdx.x, n = Dd + o;
    if (o >= NOBS) {
        for (int k = tid; k < K2; k += 256) {
            g_B2h[n * K2 + k] = __float2bfloat16(0.f);
            g_B2l[n * K2 + k] = __float2bfloat16(0.f);
        }
        if (tid == 0) g_bias2[n] = 0.f;
        return;
    }
    sC[tid] = C[o * Dd + tid];
    __syncthreads();
    for (int k = tid; k < K2; k += 256) {
        float s;
        if (k < HALL) {
            s = 0.f;
            #pragma unroll 8
            for (int d = 0; d < Dd; d++) s += sC[d] * g_Pf[d * HALL + k];
        } else {
            int u = k - HALL;
            s = Dm[o * UD + u];
            #pragma unroll 8
            for (int d = 0; d < Dd; d++) s += sC[d] * g_Mu[d * UD + u];
        }
        split2(s, g_B2h[n * K2 + k], g_B2l[n * K2 + k]);
    }
    if (tid == 0) {
        float s = 0.f;
        #pragma unroll 8
        for (int d = 0; d < Dd; d++) s += sC[d] * g_zbias[d];
        g_bias2[n] = s;
    }
}

// ======================= main kernel =======================
__global__ __launch_bounds__(256, 1) void skolr2(
    const float* __restrict__ z_dyn, const float* __restrict__ z_static,
    const float* __restrict__ dtp,   const float* __restrict__ ut,
    const float* __restrict__ b1g,   const float* __restrict__ gammag,
    const float* __restrict__ betag, float* __restrict__ out)
{
    extern __shared__ char sm[];
    const uint32_t smb = smem_u32(sm);
    const int tid = threadIdx.x, w = tid >> 5, lane = tid & 31;
    const int wm = w >> 1, wn = w & 1;
    const int g = lane >> 2, t4 = lane & 3;
    const int row0 = blockIdx.x * TM;
    const float dt = dtp[0];

    const int sub = lane >> 3;
    const uint32_t aRow = ((uint32_t)(sub & 1)) * 8 + (lane & 7);
    const uint32_t aCh  = ((uint32_t)(sub >> 1)) * 16;
    const uint32_t bRow = ((uint32_t)(sub >> 1)) * 8 + (lane & 7);
    const uint32_t bCh  = ((uint32_t)(sub & 1)) * 16;

    // ---- u*dt into H columns 512..527 (hi/lo planes) ----
    {
        int m = tid >> 2, q = tid & 3;
        float4 f = *(const float4*)&ut[(size_t)(row0 + m) * UD + q * 4];
        f.x *= dt; f.y *= dt; f.z *= dt; f.w *= dt;
        __nv_bfloat16 h0, l0, h1, l1, h2, l2, h3, l3;
        split2(f.x, h0, l0); split2(f.y, h1, l1); split2(f.z, h2, l2); split2(f.w, h3, l3);
        uint2 hp, lp;
        hp.x = (uint32_t)__bfloat16_as_ushort(h0) | ((uint32_t)__bfloat16_as_ushort(h1) << 16);
        hp.y = (uint32_t)__bfloat16_as_ushort(h2) | ((uint32_t)__bfloat16_as_ushort(h3) << 16);
        lp.x = (uint32_t)__bfloat16_as_ushort(l0) | ((uint32_t)__bfloat16_as_ushort(l1) << 16);
        lp.y = (uint32_t)__bfloat16_as_ushort(l2) | ((uint32_t)__bfloat16_as_ushort(l3) << 16);
        *(uint2*)(sm + m * HSTR + 1024 + q * 8)      = hp;
        *(uint2*)(sm + HP + m * HSTR + 1024 + q * 8) = lp;
    }

    // ================= GEMM1 (2 halves) + fused LN/GELU =================
    for (int p = 0; p < 2; p++) {
        float acc[16][4];
        #pragma unroll
        for (int i = 0; i < 16; i++) { acc[i][0] = acc[i][1] = acc[i][2] = acc[i][3] = 0.f; }

        #define STAGE1(kc_, buf_) do { \
            int _kc = (kc_), _bf = (buf_); \
            { int m = tid >> 2, q = tid & 3; \
              float4 f = (_kc < 16) \
                ? *(const float4*)&z_dyn[(size_t)(row0 + m) * Dd + _kc * 16 + q * 4] \
                : *(const float4*)&z_static[(size_t)(row0 + m) * SDIM + (_kc - 16) * 16 + q * 4]; \
              __nv_bfloat16 h0, l0, h1, l1, h2, l2, h3, l3; \
              split2(f.x, h0, l0); split2(f.y, h1, l1); split2(f.z, h2, l2); split2(f.w, h3, l3); \
              uint2 hp, lp; \
              hp.x = (uint32_t)__bfloat16_as_ushort(h0) | ((uint32_t)__bfloat16_as_ushort(h1) << 16); \
              hp.y = (uint32_t)__bfloat16_as_ushort(h2) | ((uint32_t)__bfloat16_as_ushort(h3) << 16); \
              lp.x = (uint32_t)__bfloat16_as_ushort(l0) | ((uint32_t)__bfloat16_as_ushort(l1) << 16); \
              lp.y = (uint32_t)__bfloat16_as_ushort(l2) | ((uint32_t)__bfloat16_as_ushort(l3) << 16); \
              char* ab = sm + OFF_AB + _bf * ABUF + m * 48 + q * 8; \
              *(uint2*)ab = hp; *(uint2*)(ab + APL) = lp; } \
            _Pragma("unroll") \
            for (int t = 0; t < 4; t++) { \
                int comp = tid + t * 256; \
                int n = comp & 255, h16 = (comp >> 8) & 1, pl = comp >> 9; \
                const __nv_bfloat16* src = (pl ? g_W1l : g_W1h) + (size_t)(p * 256 + n) * MEAS + _kc * 16 + h16 * 8; \
                uint32_t dst = smb + OFF_BB + _bf * BBUF + pl * BPL + n * 48 + h16 * 16; \
                CPA(dst, src); \
            } \
        } while (0)

        STAGE1(0, 0); CPC();
        for (int kc = 0; kc < 20; kc++) {
            if (kc < 19) { STAGE1(kc + 1, (kc + 1) & 1); CPC(); CPW1(); } else { CPW0(); }
            __syncthreads();
            const int buf = kc & 1;
            uint32_t ah[4], al[4];
            uint32_t aaddr = smb + OFF_AB + buf * ABUF + (wm * 16 + aRow) * 48 + aCh;
            LDSM4(ah, aaddr); LDSM4(al, aaddr + APL);
            uint32_t bbase = smb + OFF_BB + buf * BBUF + (wn * 128 + bRow) * 48 + bCh;
            #pragma unroll
            for (int q = 0; q < 8; q++) {
                uint32_t bh[4], bl[4];
                uint32_t ba = bbase + q * (16 * 48);
                LDSM4(bh, ba); LDSM4(bl, ba + BPL);
                mma_bf16(acc[q * 2],     ah, bh);     mma_bf16(acc[q * 2],     ah, bl);
                mma_bf16(acc[q * 2],     al, bh);
                mma_bf16(acc[q * 2 + 1], ah, bh + 2); mma_bf16(acc[q * 2 + 1], ah, bl + 2);
                mma_bf16(acc[q * 2 + 1], al, bh + 2);
            }
            __syncthreads();
        }
        #undef STAGE1

        // ---- epilogue: +b1, LN(128), GELU, split -> H ----
        float s0 = 0.f, q0 = 0.f, s1 = 0.f, q1 = 0.f;
        #pragma unroll
        for (int nt = 0; nt < 16; nt++) {
            int c = p * 256 + wn * 128 + nt * 8 + t4 * 2;
            float2 bv = __ldg((const float2*)&b1g[c]);
            acc[nt][0] += bv.x; acc[nt][1] += bv.y; acc[nt][2] += bv.x; acc[nt][3] += bv.y;
            s0 += acc[nt][0] + acc[nt][1];
            q0 = fmaf(acc[nt][0], acc[nt][0], fmaf(acc[nt][1], acc[nt][1], q0));
            s1 += acc[nt][2] + acc[nt][3];
            q1 = fmaf(acc[nt][2], acc[nt][2], fmaf(acc[nt][3], acc[nt][3], q1));
        }
        #pragma unroll
        for (int o = 1; o <= 2; o <<= 1) {
            s0 += __shfl_xor_sync(0xffffffffu, s0, o);
            q0 += __shfl_xor_sync(0xffffffffu, q0, o);
            s1 += __shfl_xor_sync(0xffffffffu, s1, o);
            q1 += __shfl_xor_sync(0xffffffffu, q1, o);
        }
        const float mean0 = s0 * (1.f / 128.f);
        const float inv0  = rsqrtf(q0 * (1.f / 128.f) - mean0 * mean0 + 1e-5f);
        const float mean1 = s1 * (1.f / 128.f);
        const float inv1  = rsqrtf(q1 * (1.f / 128.f) - mean1 * mean1 + 1e-5f);
        const int rA = wm * 16 + g, rB = rA + 8;
        #pragma unroll
        for (int nt = 0; nt < 16; nt++) {
            int c = p * 256 + wn * 128 + nt * 8 + t4 * 2;
            float2 gv = __ldg((const float2*)&gammag[c]);
            float2 ev = __ldg((const float2*)&betag[c]);
            float t0 = (acc[nt][0] - mean0) * inv0 * gv.x + ev.x;
            float t1 = (acc[nt][1] - mean0) * inv0 * gv.y + ev.y;
            float t2 = (acc[nt][2] - mean1) * inv1 * gv.x + ev.x;
            float t3 = (acc[nt][3] - mean1) * inv1 * gv.y + ev.y;
            t0 = 0.5f * t0 * (1.f + erff(t0 * 0.70710678118654752f));
            t1 = 0.5f * t1 * (1.f + erff(t1 * 0.70710678118654752f));
            t2 = 0.5f * t2 * (1.f + erff(t2 * 0.70710678118654752f));
            t3 = 0.5f * t3 * (1.f + erff(t3 * 0.70710678118654752f));
            __nv_bfloat16 x0, y0, x1, y1, x2, y2, x3, y3;
            split2(t0, x0, y0); split2(t1, x1, y1); split2(t2, x2, y2); split2(t3, x3, y3);
            uint32_t hA = (uint32_t)__bfloat16_as_ushort(x0) | ((uint32_t)__bfloat16_as_ushort(x1) << 16);
            uint32_t lA = (uint32_t)__bfloat16_as_ushort(y0) | ((uint32_t)__bfloat16_as_ushort(y1) << 16);
            uint32_t hB = (uint32_t)__bfloat16_as_ushort(x2) | ((uint32_t)__bfloat16_as_ushort(x3) << 16);
            uint32_t lB = (uint32_t)__bfloat16_as_ushort(y2) | ((uint32_t)__bfloat16_as_ushort(y3) << 16);
            *(uint32_t*)(sm + rA * HSTR + c * 2)      = hA;
            *(uint32_t*)(sm + HP + rA * HSTR + c * 2) = lA;
            *(uint32_t*)(sm + rB * HSTR + c * 2)      = hB;
            *(uint32_t*)(sm + HP + rB * HSTR + c * 2) = lB;
        }
    }

    // ================= GEMM2: [64][288] = H[64][528] x B2^T =================
    float acc2[18][4];
    #pragma unroll
    for (int i = 0; i < 18; i++) { acc2[i][0] = acc2[i][1] = acc2[i][2] = acc2[i][3] = 0.f; }

    #define STAGE2(kc_, buf_) do { \
        int _kc = (kc_), _bf = (buf_); \
        for (int idx = tid; idx < 1152; idx += 256) { \
            int pl = idx / 576, rem = idx % 576, n = rem >> 1, h16 = rem & 1; \
            const __nv_bfloat16* src = (pl ? g_B2l : g_B2h) + (size_t)n * K2 + _kc * 16 + h16 * 8; \
            uint32_t dst = smb + OFF_BB + _bf * BBUF + pl * BPL + n * 48 + h16 * 16; \
            CPA(dst, src); \
        } \
    } while (0)

    STAGE2(0, 0); CPC();
    for (int kc = 0; kc < 33; kc++) {
        if (kc < 32) { STAGE2(kc + 1, (kc + 1) & 1); CPC(); CPW1(); } else { CPW0(); }
        __syncthreads();
        const int buf = kc & 1;
        uint32_t ah[4], al[4];
        uint32_t aaddr = smb + (wm * 16 + aRow) * HSTR + kc * 32 + aCh;
        LDSM4(ah, aaddr); LDSM4(al, aaddr + HP);
        uint32_t bbase = smb + OFF_BB + buf * BBUF + (wn * 144 + bRow) * 48 + bCh;
        #pragma unroll
        for (int q = 0; q < 9; q++) {
            uint32_t bh[4], bl[4];
            uint32_t ba = bbase + q * (16 * 48);
            LDSM4(bh, ba); LDSM4(bl, ba + BPL);
            mma_bf16(acc2[q * 2],     ah, bh);     mma_bf16(acc2[q * 2],     ah, bl);
            mma_bf16(acc2[q * 2],     al, bh);
            mma_bf16(acc2[q * 2 + 1], ah, bh + 2); mma_bf16(acc2[q * 2 + 1], ah, bl + 2);
            mma_bf16(acc2[q * 2 + 1], al, bh + 2);
        }
        __syncthreads();
    }
    #undef STAGE2

    // ---- epilogue: +bias2; write z_next and yt ----
    float* out_yt = out + (size_t)BSZ * Dd;
    #pragma unroll
    for (int nt = 0; nt < 18; nt++) {
        const int n0 = wn * 144 + nt * 8 + t4 * 2;
        float2 bv = __ldg((const float2*)&g_bias2[n0]);
        const int r = wm * 16 + g;
        float v0 = acc2[nt][0] + bv.x, v1 = acc2[nt][1] + bv.y;
        float v2 = acc2[nt][2] + bv.x, v3 = acc2[nt][3] + bv.y;
        if (n0 < Dd) {
            *(float2*)&out[(size_t)(row0 + r) * Dd + n0]     = make_float2(v0, v1);
            *(float2*)&out[(size_t)(row0 + r + 8) * Dd + n0] = make_float2(v2, v3);
        } else {
            const int o = n0 - Dd;
            if (o < NOBS)     { out_yt[(size_t)(row0 + r) * NOBS + o]     = v0;
                                out_yt[(size_t)(row0 + r + 8) * NOBS + o] = v2; }
            if (o + 1 < NOBS) { out_yt[(size_t)(row0 + r) * NOBS + o + 1]     = v1;
                                out_yt[(size_t)(row0 + r + 8) * NOBS + o + 1] = v3; }
        }
    }
}

extern "C" void kernel_launch(void* const* d_in, const int* in_sizes, int n_in,
                              void* d_out, int out_size) {
    const float* z_dyn    = (const float*)d_in[0];
    const float* z_static = (const float*)d_in[1];
    const float* dt       = (const float*)d_in[2];
    const float* ut       = (const float*)d_in[3];
    const float* gates    = (const float*)d_in[4];
    const float* W1       = (const float*)d_in[5];
    const float* b1       = (const float*)d_in[6];
    const float* gamma    = (const float*)d_in[7];
    const float* beta     = (const float*)d_in[8];
    const float* W2       = (const float*)d_in[9];
    const float* b2       = (const float*)d_in[10];
    const float* Bmat     = (const float*)d_in[13];
    const float* Wout     = (const float*)d_in[14];
    const float* Cmat     = (const float*)d_in[15];
    const float* Dm       = (const float*)d_in[16];
    float* out = (float*)d_out;

    pre_w1<<<(HALL * MEAS + 255) / 256, 256>>>(W1, gates);
    pre_M_Mu<<<(NBR * Dd * RH + Dd * UD + 255) / 256, 256>>>(Wout, Bmat);
    pre_P<<<(NBR * Dd * MH + Dd + 255) / 256, 256>>>(W2, b2);
    pre_B2a<<<(Dd * K2 + 255) / 256, 256>>>();
    pre_B2b<<<N2 - Dd, 256>>>(Cmat, Dm);

    cudaFuncSetAttribute(skolr2, cudaFuncAttributeMaxDynamicSharedMemorySize, SMEM_TOTAL);
    skolr2<<<BSZ / TM, 256, SMEM_TOTAL>>>(z_dyn, z_static, dt, ut, b1, gamma, beta, out);
}